// round 14
// baseline (speedup 1.0000x reference)
#include <cuda_runtime.h>
#include <cuda_fp16.h>
#include <math.h>
#include <stdint.h>

#define NN    50000
#define NE    640000
#define IND   128
#define OUTD  128
#define EDIM  16
#define NH    4
#define HD    32
#define NB    ((NN + 511) / 512)   // scan blocks = 98

#define SWS   132                  // padded smem row stride (floats)
#define GEMM_SMEM ((128 * SWS + 64 * SWS) * 4)

// ---------------- scratch (device globals; no runtime alloc allowed) -------
__device__ __align__(16) __half g_Whh[NN * OUTD]; // fp16 projected features
__device__ __align__(16) float g_ssrc[NN * NH];
__device__ __align__(16) float g_sdst[NN * NH];
__device__ __align__(16) float g_attn2[NE * NH];   // exp values, CSR order
__device__ int   g_csrc[NE];                       // src node, CSR order
__device__ int   g_rank[NE];                       // rank of edge within dst
__device__ int   g_cnt[NN];
__device__ int   g_off[NN + 1];                    // partial (per-block) excl scan
__device__ int   g_bsum[128];                      // excl block sums
__device__ int   g_is64;

__device__ __forceinline__ int load_idx(const int* p32, int i, int is64) {
    return is64 ? p32[2 * i] : p32[i];   // int64 LE, values < 2^31
}

__device__ __forceinline__ int off_final(int i) {
    return g_off[i] + g_bsum[i >> 9];
}

// ---------------- tf32 helpers ---------------------------------------------
__device__ __forceinline__ uint32_t f2tf32(float x) {
    uint32_t r;
    asm("cvt.rna.tf32.f32 %0, %1;" : "=r"(r) : "f"(x));
    return r;
}
__device__ __forceinline__ void tf32_split(float x, uint32_t& hi, uint32_t& lo) {
    hi = f2tf32(x);
    lo = f2tf32(x - __uint_as_float(hi));
}
__device__ __forceinline__ void mma_tf32(float4& c, const uint32_t* a, const uint32_t* b) {
    asm volatile(
        "mma.sync.aligned.m16n8k8.row.col.f32.tf32.tf32.f32 "
        "{%0,%1,%2,%3}, {%4,%5,%6,%7}, {%8,%9}, {%0,%1,%2,%3};"
        : "+f"(c.x), "+f"(c.y), "+f"(c.z), "+f"(c.w)
        : "r"(a[0]), "r"(a[1]), "r"(a[2]), "r"(a[3]), "r"(b[0]), "r"(b[1]));
}

// ---------------- detect edge_index dtype + zero counts ---------------------
__global__ void k_prep(const int* __restrict__ ei32) {
    int t = blockIdx.x * blockDim.x + threadIdx.x;
    if (t < NN) g_cnt[t] = 0;
    if (t == 0) {
        int nz = 0;
        #pragma unroll 4
        for (int k = 0; k < 2048; k++) nz |= ei32[2 * k + 1];
        g_is64 = (nz == 0) ? 1 : 0;
    }
}

// ---------------- per-edge dst count + rank ---------------------------------
__global__ void k_count(const int* __restrict__ ei) {
    int e = blockIdx.x * blockDim.x + threadIdx.x;
    if (e >= NE) return;
    int dst = load_idx(ei, NE + e, g_is64);
    g_rank[e] = atomicAdd(&g_cnt[dst], 1);
}

// ---------------- Wh = h @ W^T via split-tf32 MMA (plain epilogue) ---------
// block: 64 nodes x 128 outs, 8 warps (4 m-warps x 2 n-warps), K=128
__global__ void k_gemm(const float* __restrict__ h, const float* __restrict__ W) {
    extern __shared__ float smem[];
    float* sW = smem;                 // [128][SWS]  W[o][k]
    float* sH = smem + 128 * SWS;     // [64][SWS]   h[m][k]
    const int tid  = threadIdx.x;
    const int n0b  = blockIdx.x * 64;
    const int lane = tid & 31;
    const int wid  = tid >> 5;
    const int mw   = wid & 3;         // m tile: 16 rows
    const int nw   = wid >> 2;        // n half: 64 cols
    const int grp  = lane >> 2;       // 0..7
    const int tig  = lane & 3;        // 0..3

    #pragma unroll
    for (int it = 0; it < 16; it++) {
        int f = it * 256 + tid;
        int o = f >> 5, c4 = (f & 31) * 4;
        float4 v = *(const float4*)(W + o * IND + c4);
        float* d = sW + o * SWS + c4;
        d[0] = v.x; d[1] = v.y; d[2] = v.z; d[3] = v.w;
    }
    #pragma unroll
    for (int it = 0; it < 8; it++) {
        int f = it * 256 + tid;
        int m = f >> 5, c4 = (f & 31) * 4;
        float4 v = make_float4(0.f, 0.f, 0.f, 0.f);
        if (n0b + m < NN) v = *(const float4*)(h + (size_t)(n0b + m) * IND + c4);
        float* d = sH + m * SWS + c4;
        d[0] = v.x; d[1] = v.y; d[2] = v.z; d[3] = v.w;
    }
    __syncthreads();

    float4 acc[8];
    #pragma unroll
    for (int i = 0; i < 8; i++) acc[i] = make_float4(0.f, 0.f, 0.f, 0.f);

    const int m0 = mw * 16;
    const int nb0 = nw * 64;

    #pragma unroll 4
    for (int k0 = 0; k0 < IND; k0 += 8) {
        uint32_t ah[4], al[4];
        {
            float a0 = sH[(m0 + grp) * SWS + k0 + tig];
            float a1 = sH[(m0 + grp + 8) * SWS + k0 + tig];
            float a2 = sH[(m0 + grp) * SWS + k0 + tig + 4];
            float a3 = sH[(m0 + grp + 8) * SWS + k0 + tig + 4];
            tf32_split(a0, ah[0], al[0]);
            tf32_split(a1, ah[1], al[1]);
            tf32_split(a2, ah[2], al[2]);
            tf32_split(a3, ah[3], al[3]);
        }
        #pragma unroll
        for (int nt = 0; nt < 8; nt++) {
            int n = nb0 + nt * 8;
            uint32_t bh[2], bl[2];
            float b0 = sW[(n + grp) * SWS + k0 + tig];
            float b1 = sW[(n + grp) * SWS + k0 + tig + 4];
            tf32_split(b0, bh[0], bl[0]);
            tf32_split(b1, bh[1], bl[1]);
            mma_tf32(acc[nt], ah, bh);
            mma_tf32(acc[nt], ah, bl);
            mma_tf32(acc[nt], al, bh);
        }
    }

    int node0 = n0b + m0 + grp;
    int node1 = node0 + 8;
    #pragma unroll
    for (int nt = 0; nt < 8; nt++) {
        int col = nb0 + nt * 8 + 2 * tig;
        if (node0 < NN)
            *(__half2*)(g_Whh + (size_t)node0 * OUTD + col) =
                __float22half2_rn(make_float2(acc[nt].x, acc[nt].y));
        if (node1 < NN)
            *(__half2*)(g_Whh + (size_t)node1 * OUTD + col) =
                __float22half2_rn(make_float2(acc[nt].z, acc[nt].w));
    }
}

// ---------------- per-node attention score halves (warp per node, fp16) ----
__global__ void k_scores(const float* __restrict__ a) {
    int w    = (blockIdx.x * blockDim.x + threadIdx.x) >> 5;
    int lane = threadIdx.x & 31;
    if (w >= NN) return;
    uint2 u = *(const uint2*)(g_Whh + (size_t)w * OUTD + lane * 4);
    float2 p = __half22float2(*(__half2*)&u.x);
    float2 q = __half22float2(*(__half2*)&u.y);
    int   hh  = lane >> 3;
    int   d0  = (lane & 7) * 4;
    float4 a1 = *(const float4*)(a + hh * (2 * HD) + d0);
    float4 a2 = *(const float4*)(a + hh * (2 * HD) + HD + d0);
    float s1  = p.x * a1.x + p.y * a1.y + q.x * a1.z + q.y * a1.w;
    float s2  = p.x * a2.x + p.y * a2.y + q.x * a2.z + q.y * a2.w;
    #pragma unroll
    for (int o = 4; o >= 1; o >>= 1) {
        s1 += __shfl_xor_sync(0xffffffffu, s1, o);
        s2 += __shfl_xor_sync(0xffffffffu, s2, o);
    }
    if ((lane & 7) == 0) {
        g_ssrc[w * NH + hh] = s1;
        g_sdst[w * NH + hh] = s2;
    }
}

// ---------------- CSR scan: per-block partial + block-sum scan --------------
__global__ void k_scan1() {
    __shared__ int sh[512];
    int i = blockIdx.x * 512 + threadIdx.x;
    int v = (i < NN) ? g_cnt[i] : 0;
    sh[threadIdx.x] = v;
    __syncthreads();
    for (int o = 1; o < 512; o <<= 1) {
        int t = (threadIdx.x >= o) ? sh[threadIdx.x - o] : 0;
        __syncthreads();
        sh[threadIdx.x] += t;
        __syncthreads();
    }
    int incl = sh[threadIdx.x];
    if (i < NN) g_off[i] = incl - v;
    if (threadIdx.x == 511) g_bsum[blockIdx.x] = incl;
}

__global__ void k_scan2() {
    __shared__ int sh[128];
    int i = threadIdx.x;
    int v = (i < NB) ? g_bsum[i] : 0;
    sh[i] = v;
    __syncthreads();
    for (int o = 1; o < 128; o <<= 1) {
        int t = (i >= o) ? sh[i - o] : 0;
        __syncthreads();
        sh[i] += t;
        __syncthreads();
    }
    g_bsum[i] = sh[i] - v;
}

// ---------------- edge logits -> exp -> direct CSR scatter ------------------
__global__ void k_edgescatter(const int* __restrict__ ei,
                              const float* __restrict__ ef,
                              const float* __restrict__ We) {
    __shared__ float sWe[NH * EDIM];
    if (threadIdx.x < NH * EDIM) sWe[threadIdx.x] = We[threadIdx.x];
    __syncthreads();
    int e = blockIdx.x * blockDim.x + threadIdx.x;
    if (e >= NE) return;
    int is64 = g_is64;
    int src = load_idx(ei, e, is64);
    int dst = load_idx(ei, NE + e, is64);
    float4 s1 = *(const float4*)(g_ssrc + src * NH);
    float4 s2 = *(const float4*)(g_sdst + dst * NH);
    float s[4] = { s1.x + s2.x, s1.y + s2.y, s1.z + s2.z, s1.w + s2.w };
    #pragma unroll
    for (int hh = 0; hh < 4; hh++) s[hh] = (s[hh] > 0.f) ? s[hh] : 0.2f * s[hh];

    const float4* efp = (const float4*)(ef + (size_t)e * EDIM);
    float4 e0 = efp[0], e1 = efp[1], e2 = efp[2], e3 = efp[3];
    float ev[16] = { e0.x, e0.y, e0.z, e0.w, e1.x, e1.y, e1.z, e1.w,
                     e2.x, e2.y, e2.z, e2.w, e3.x, e3.y, e3.z, e3.w };
    float4 r;
    #pragma unroll
    for (int hh = 0; hh < 4; hh++) {
        float dot = 0.f;
        #pragma unroll
        for (int k = 0; k < EDIM; k++) dot += sWe[hh * EDIM + k] * ev[k];
        float v = expf(s[hh] + dot);
        ((float*)&r)[hh] = v;
    }
    int pos = off_final(dst) + g_rank[e];
    g_csrc[pos] = src;
    *(float4*)(g_attn2 + (size_t)pos * NH) = r;
}

// ---------------- gather-aggregate (fp16 feats) + softmax + gelu + LN ------
__global__ void k_aggpost(const float* __restrict__ lns,
                          const float* __restrict__ lnb,
                          float* __restrict__ out) {
    int w    = (blockIdx.x * blockDim.x + threadIdx.x) >> 5;
    int lane = threadIdx.x & 31;
    if (w >= NN) return;
    int beg = off_final(w);
    int end = (w + 1 < NN) ? off_final(w + 1) : NE;
    int hh  = lane >> 3;
    float4 acc = make_float4(0.f, 0.f, 0.f, 0.f);
    float dsum = 0.f;
    int i = beg;
    for (; i + 4 <= end; i += 4) {
        int s0 = g_csrc[i], s1 = g_csrc[i + 1], s2 = g_csrc[i + 2], s3 = g_csrc[i + 3];
        float a0 = g_attn2[(i + 0) * NH + hh];
        float a1 = g_attn2[(i + 1) * NH + hh];
        float a2 = g_attn2[(i + 2) * NH + hh];
        float a3 = g_attn2[(i + 3) * NH + hh];
        uint2 u0 = *(const uint2*)(g_Whh + (size_t)s0 * OUTD + lane * 4);
        uint2 u1 = *(const uint2*)(g_Whh + (size_t)s1 * OUTD + lane * 4);
        uint2 u2 = *(const uint2*)(g_Whh + (size_t)s2 * OUTD + lane * 4);
        uint2 u3 = *(const uint2*)(g_Whh + (size_t)s3 * OUTD + lane * 4);
        float2 p0 = __half22float2(*(__half2*)&u0.x), q0 = __half22float2(*(__half2*)&u0.y);
        float2 p1 = __half22float2(*(__half2*)&u1.x), q1 = __half22float2(*(__half2*)&u1.y);
        float2 p2 = __half22float2(*(__half2*)&u2.x), q2 = __half22float2(*(__half2*)&u2.y);
        float2 p3 = __half22float2(*(__half2*)&u3.x), q3 = __half22float2(*(__half2*)&u3.y);
        acc.x += a0 * p0.x + a1 * p1.x + a2 * p2.x + a3 * p3.x;
        acc.y += a0 * p0.y + a1 * p1.y + a2 * p2.y + a3 * p3.y;
        acc.z += a0 * q0.x + a1 * q1.x + a2 * q2.x + a3 * q3.x;
        acc.w += a0 * q0.y + a1 * q1.y + a2 * q2.y + a3 * q3.y;
        dsum  += a0 + a1 + a2 + a3;
    }
    for (; i < end; i++) {
        int s0 = g_csrc[i];
        float a0 = g_attn2[i * NH + hh];
        uint2 u0 = *(const uint2*)(g_Whh + (size_t)s0 * OUTD + lane * 4);
        float2 p0 = __half22float2(*(__half2*)&u0.x), q0 = __half22float2(*(__half2*)&u0.y);
        acc.x += a0 * p0.x; acc.y += a0 * p0.y;
        acc.z += a0 * q0.x; acc.w += a0 * q0.y;
        dsum  += a0;
    }
    float inv = 1.f / (dsum + 1e-9f);
    float x0 = acc.x * inv, x1 = acc.y * inv, x2 = acc.z * inv, x3 = acc.w * inv;
    float g0 = 0.5f * x0 * (1.f + erff(x0 * 0.70710678118654752f));
    float g1 = 0.5f * x1 * (1.f + erff(x1 * 0.70710678118654752f));
    float g2 = 0.5f * x2 * (1.f + erff(x2 * 0.70710678118654752f));
    float g3 = 0.5f * x3 * (1.f + erff(x3 * 0.70710678118654752f));
    float s = g0 + g1 + g2 + g3;
    #pragma unroll
    for (int o = 16; o > 0; o >>= 1) s += __shfl_xor_sync(0xffffffffu, s, o);
    float mu = s * (1.f / OUTD);
    float d0 = g0 - mu, d1 = g1 - mu, d2 = g2 - mu, d3 = g3 - mu;
    float ss = d0 * d0 + d1 * d1 + d2 * d2 + d3 * d3;
    #pragma unroll
    for (int o = 16; o > 0; o >>= 1) ss += __shfl_xor_sync(0xffffffffu, ss, o);
    float invs = rsqrtf(ss * (1.f / OUTD) + 1e-5f);
    float4 sc = *(const float4*)(lns + lane * 4);
    float4 bi = *(const float4*)(lnb + lane * 4);
    float4 r;
    r.x = d0 * invs * sc.x + bi.x;
    r.y = d1 * invs * sc.y + bi.y;
    r.z = d2 * invs * sc.z + bi.z;
    r.w = d3 * invs * sc.w + bi.w;
    *(float4*)(out + (size_t)w * OUTD + lane * 4) = r;
}

// ---------------- launch ----------------------------------------------------
extern "C" void kernel_launch(void* const* d_in, const int* in_sizes, int n_in,
                              void* d_out, int out_size) {
    const float* h   = (const float*)d_in[0];
    const int*   ei  = (const int*)d_in[1];
    const float* ef  = (const float*)d_in[2];
    const float* W   = (const float*)d_in[3];
    const float* We  = (const float*)d_in[4];
    const float* a   = (const float*)d_in[5];
    const float* lns = (const float*)d_in[6];
    const float* lnb = (const float*)d_in[7];
    float* out = (float*)d_out;

    cudaFuncSetAttribute(k_gemm, cudaFuncAttributeMaxDynamicSharedMemorySize, GEMM_SMEM);

    k_prep<<<(NN + 255) / 256, 256>>>(ei);
    k_count<<<(NE + 255) / 256, 256>>>(ei);
    k_gemm<<<(NN + 63) / 64, 256, GEMM_SMEM>>>(h, W);
    k_scores<<<(NN * 32 + 255) / 256, 256>>>(a);
    k_scan1<<<NB, 512>>>();
    k_scan2<<<1, 128>>>();
    k_edgescatter<<<(NE + 255) / 256, 256>>>(ei, ef, We);
    k_aggpost<<<(NN * 32 + 255) / 256, 256>>>(lns, lnb, out);
}

// round 15
// speedup vs baseline: 1.1638x; 1.1638x over previous
#include <cuda_runtime.h>
#include <cuda_fp16.h>
#include <math.h>
#include <stdint.h>

#define NN    50000
#define NE    640000
#define IND   128
#define OUTD  128
#define EDIM  16
#define NH    4
#define HD    32
#define NB    ((NN + 511) / 512)   // scan blocks = 98

#define SWS   132                  // padded smem row stride (floats)
#define GEMM_SMEM ((128 * SWS + 64 * SWS) * 4)

// ---------------- scratch (device globals; no runtime alloc allowed) -------
__device__ __align__(16) __half g_Whh[NN * OUTD]; // fp16 projected features
__device__ __align__(16) float g_ssrc[NN * NH];
__device__ __align__(16) float g_sdst[NN * NH];
__device__ __align__(16) float g_attn[NE * NH];    // exp values, edge order
__device__ __align__(16) float g_attn2[NE * NH];   // exp values, CSR order
__device__ int   g_csrc[NE];                       // src node, CSR order
__device__ int   g_rank[NE];                       // rank of edge within dst
__device__ int   g_cnt[NN];
__device__ int   g_off[NN + 1];
__device__ int   g_bsum[128];
__device__ int   g_is64;

__device__ __forceinline__ int load_idx(const int* p32, int i, int is64) {
    return is64 ? p32[2 * i] : p32[i];   // int64 LE, values < 2^31
}

// ---------------- tf32 helpers ---------------------------------------------
__device__ __forceinline__ uint32_t f2tf32(float x) {
    uint32_t r;
    asm("cvt.rna.tf32.f32 %0, %1;" : "=r"(r) : "f"(x));
    return r;
}
__device__ __forceinline__ void tf32_split(float x, uint32_t& hi, uint32_t& lo) {
    hi = f2tf32(x);
    lo = f2tf32(x - __uint_as_float(hi));
}
__device__ __forceinline__ void mma_tf32(float4& c, const uint32_t* a, const uint32_t* b) {
    asm volatile(
        "mma.sync.aligned.m16n8k8.row.col.f32.tf32.tf32.f32 "
        "{%0,%1,%2,%3}, {%4,%5,%6,%7}, {%8,%9}, {%0,%1,%2,%3};"
        : "+f"(c.x), "+f"(c.y), "+f"(c.z), "+f"(c.w)
        : "r"(a[0]), "r"(a[1]), "r"(a[2]), "r"(a[3]), "r"(b[0]), "r"(b[1]));
}

// ---------------- detect edge_index dtype + zero counts ---------------------
__global__ void k_prep(const int* __restrict__ ei32) {
    int t = blockIdx.x * blockDim.x + threadIdx.x;
    if (t < NN) g_cnt[t] = 0;
    if (t == 0) {
        int nz = 0;
        #pragma unroll 4
        for (int k = 0; k < 2048; k++) nz |= ei32[2 * k + 1];
        g_is64 = (nz == 0) ? 1 : 0;
    }
}

// ---------------- Wh = h @ W^T via split-tf32 MMA (plain epilogue) ---------
// block: 64 nodes x 128 outs, 8 warps (4 m-warps x 2 n-warps), K=128
__global__ void k_gemm(const float* __restrict__ h, const float* __restrict__ W) {
    extern __shared__ float smem[];
    float* sW = smem;                 // [128][SWS]  W[o][k]
    float* sH = smem + 128 * SWS;     // [64][SWS]   h[m][k]
    const int tid  = threadIdx.x;
    const int n0b  = blockIdx.x * 64;
    const int lane = tid & 31;
    const int wid  = tid >> 5;
    const int mw   = wid & 3;         // m tile: 16 rows
    const int nw   = wid >> 2;        // n half: 64 cols
    const int grp  = lane >> 2;       // 0..7
    const int tig  = lane & 3;        // 0..3

    #pragma unroll
    for (int it = 0; it < 16; it++) {
        int f = it * 256 + tid;
        int o = f >> 5, c4 = (f & 31) * 4;
        float4 v = *(const float4*)(W + o * IND + c4);
        float* d = sW + o * SWS + c4;
        d[0] = v.x; d[1] = v.y; d[2] = v.z; d[3] = v.w;
    }
    #pragma unroll
    for (int it = 0; it < 8; it++) {
        int f = it * 256 + tid;
        int m = f >> 5, c4 = (f & 31) * 4;
        float4 v = make_float4(0.f, 0.f, 0.f, 0.f);
        if (n0b + m < NN) v = *(const float4*)(h + (size_t)(n0b + m) * IND + c4);
        float* d = sH + m * SWS + c4;
        d[0] = v.x; d[1] = v.y; d[2] = v.z; d[3] = v.w;
    }
    __syncthreads();

    float4 acc[8];
    #pragma unroll
    for (int i = 0; i < 8; i++) acc[i] = make_float4(0.f, 0.f, 0.f, 0.f);

    const int m0 = mw * 16;
    const int nb0 = nw * 64;

    #pragma unroll 4
    for (int k0 = 0; k0 < IND; k0 += 8) {
        uint32_t ah[4], al[4];
        {
            float a0 = sH[(m0 + grp) * SWS + k0 + tig];
            float a1 = sH[(m0 + grp + 8) * SWS + k0 + tig];
            float a2 = sH[(m0 + grp) * SWS + k0 + tig + 4];
            float a3 = sH[(m0 + grp + 8) * SWS + k0 + tig + 4];
            tf32_split(a0, ah[0], al[0]);
            tf32_split(a1, ah[1], al[1]);
            tf32_split(a2, ah[2], al[2]);
            tf32_split(a3, ah[3], al[3]);
        }
        #pragma unroll
        for (int nt = 0; nt < 8; nt++) {
            int n = nb0 + nt * 8;
            uint32_t bh[2], bl[2];
            float b0 = sW[(n + grp) * SWS + k0 + tig];
            float b1 = sW[(n + grp) * SWS + k0 + tig + 4];
            tf32_split(b0, bh[0], bl[0]);
            tf32_split(b1, bh[1], bl[1]);
            mma_tf32(acc[nt], ah, bh);
            mma_tf32(acc[nt], ah, bl);
            mma_tf32(acc[nt], al, bh);
        }
    }

    int node0 = n0b + m0 + grp;
    int node1 = node0 + 8;
    #pragma unroll
    for (int nt = 0; nt < 8; nt++) {
        int col = nb0 + nt * 8 + 2 * tig;
        if (node0 < NN)
            *(__half2*)(g_Whh + (size_t)node0 * OUTD + col) =
                __float22half2_rn(make_float2(acc[nt].x, acc[nt].y));
        if (node1 < NN)
            *(__half2*)(g_Whh + (size_t)node1 * OUTD + col) =
                __float22half2_rn(make_float2(acc[nt].z, acc[nt].w));
    }
}

// ---------------- per-node attention score halves (warp per node, fp16) ----
__global__ void k_scores(const float* __restrict__ a) {
    int w    = (blockIdx.x * blockDim.x + threadIdx.x) >> 5;
    int lane = threadIdx.x & 31;
    if (w >= NN) return;
    uint2 u = *(const uint2*)(g_Whh + (size_t)w * OUTD + lane * 4);
    float2 p = __half22float2(*(__half2*)&u.x);
    float2 q = __half22float2(*(__half2*)&u.y);
    int   hh  = lane >> 3;
    int   d0  = (lane & 7) * 4;
    float4 a1 = *(const float4*)(a + hh * (2 * HD) + d0);
    float4 a2 = *(const float4*)(a + hh * (2 * HD) + HD + d0);
    float s1  = p.x * a1.x + p.y * a1.y + q.x * a1.z + q.y * a1.w;
    float s2  = p.x * a2.x + p.y * a2.y + q.x * a2.z + q.y * a2.w;
    #pragma unroll
    for (int o = 4; o >= 1; o >>= 1) {
        s1 += __shfl_xor_sync(0xffffffffu, s1, o);
        s2 += __shfl_xor_sync(0xffffffffu, s2, o);
    }
    if ((lane & 7) == 0) {
        g_ssrc[w * NH + hh] = s1;
        g_sdst[w * NH + hh] = s2;
    }
}

// ---------------- edge logits -> exp (4 heads per thread) + count/rank -----
__global__ void k_edge(const int* __restrict__ ei,
                       const float* __restrict__ ef,
                       const float* __restrict__ We) {
    __shared__ float sWe[NH * EDIM];
    if (threadIdx.x < NH * EDIM) sWe[threadIdx.x] = We[threadIdx.x];
    __syncthreads();
    int e = blockIdx.x * blockDim.x + threadIdx.x;
    if (e >= NE) return;
    int is64 = g_is64;
    int src = load_idx(ei, e, is64);
    int dst = load_idx(ei, NE + e, is64);
    float4 s1 = *(const float4*)(g_ssrc + src * NH);
    float4 s2 = *(const float4*)(g_sdst + dst * NH);
    float s[4] = { s1.x + s2.x, s1.y + s2.y, s1.z + s2.z, s1.w + s2.w };
    #pragma unroll
    for (int hh = 0; hh < 4; hh++) s[hh] = (s[hh] > 0.f) ? s[hh] : 0.2f * s[hh];

    const float4* efp = (const float4*)(ef + (size_t)e * EDIM);
    float4 e0 = efp[0], e1 = efp[1], e2 = efp[2], e3 = efp[3];
    float ev[16] = { e0.x, e0.y, e0.z, e0.w, e1.x, e1.y, e1.z, e1.w,
                     e2.x, e2.y, e2.z, e2.w, e3.x, e3.y, e3.z, e3.w };
    float4 r;
    #pragma unroll
    for (int hh = 0; hh < 4; hh++) {
        float dot = 0.f;
        #pragma unroll
        for (int k = 0; k < EDIM; k++) dot += sWe[hh * EDIM + k] * ev[k];
        float v = expf(s[hh] + dot);
        ((float*)&r)[hh] = v;
    }
    *(float4*)(g_attn + (size_t)e * NH) = r;
    g_rank[e] = atomicAdd(&g_cnt[dst], 1);
}

// ---------------- CSR build: scan (3 kernels) + atomic-free scatter ---------
__global__ void k_scan1() {
    __shared__ int sh[512];
    int i = blockIdx.x * 512 + threadIdx.x;
    int v = (i < NN) ? g_cnt[i] : 0;
    sh[threadIdx.x] = v;
    __syncthreads();
    for (int o = 1; o < 512; o <<= 1) {
        int t = (threadIdx.x >= o) ? sh[threadIdx.x - o] : 0;
        __syncthreads();
        sh[threadIdx.x] += t;
        __syncthreads();
    }
    int incl = sh[threadIdx.x];
    if (i < NN) g_off[i] = incl - v;
    if (threadIdx.x == 511) g_bsum[blockIdx.x] = incl;
}

__global__ void k_scan2() {
    __shared__ int sh[128];
    int i = threadIdx.x;
    int v = (i < NB) ? g_bsum[i] : 0;
    sh[i] = v;
    __syncthreads();
    for (int o = 1; o < 128; o <<= 1) {
        int t = (i >= o) ? sh[i - o] : 0;
        __syncthreads();
        sh[i] += t;
        __syncthreads();
    }
    g_bsum[i] = sh[i] - v;
    if (i == 0) g_off[NN] = NE;
}

__global__ void k_scan3() {
    int i = blockIdx.x * blockDim.x + threadIdx.x;
    if (i >= NN) return;
    g_off[i] = g_off[i] + g_bsum[i >> 9];
}

__global__ void k_scatter(const int* __restrict__ ei) {
    int e = blockIdx.x * blockDim.x + threadIdx.x;
    if (e >= NE) return;
    int is64 = g_is64;
    int src = load_idx(ei, e, is64);
    int dst = load_idx(ei, NE + e, is64);
    int pos = g_off[dst] + g_rank[e];
    g_csrc[pos] = src;
    float4 v = *(const float4*)(g_attn + (size_t)e * NH);
    *(float4*)(g_attn2 + (size_t)pos * NH) = v;
}

// ---------------- gather-aggregate (fp16 feats) + softmax + gelu + LN ------
__global__ void k_aggpost(const float* __restrict__ lns,
                          const float* __restrict__ lnb,
                          float* __restrict__ out) {
    int w    = (blockIdx.x * blockDim.x + threadIdx.x) >> 5;
    int lane = threadIdx.x & 31;
    if (w >= NN) return;
    int beg = g_off[w], end = g_off[w + 1];
    int hh  = lane >> 3;
    float4 acc = make_float4(0.f, 0.f, 0.f, 0.f);
    float dsum = 0.f;
    int i = beg;
    // unroll-8: batch all loads first (MLP=8), then FMAs
    for (; i + 8 <= end; i += 8) {
        int   sid[8];
        float av[8];
        uint2 uv[8];
        #pragma unroll
        for (int j = 0; j < 8; j++) sid[j] = g_csrc[i + j];
        #pragma unroll
        for (int j = 0; j < 8; j++) av[j] = g_attn2[(i + j) * NH + hh];
        #pragma unroll
        for (int j = 0; j < 8; j++)
            uv[j] = *(const uint2*)(g_Whh + (size_t)sid[j] * OUTD + lane * 4);
        #pragma unroll
        for (int j = 0; j < 8; j++) {
            float2 p = __half22float2(*(__half2*)&uv[j].x);
            float2 q = __half22float2(*(__half2*)&uv[j].y);
            acc.x += av[j] * p.x; acc.y += av[j] * p.y;
            acc.z += av[j] * q.x; acc.w += av[j] * q.y;
            dsum  += av[j];
        }
    }
    if (i + 4 <= end) {
        int   sid[4];
        float av[4];
        uint2 uv[4];
        #pragma unroll
        for (int j = 0; j < 4; j++) sid[j] = g_csrc[i + j];
        #pragma unroll
        for (int j = 0; j < 4; j++) av[j] = g_attn2[(i + j) * NH + hh];
        #pragma unroll
        for (int j = 0; j < 4; j++)
            uv[j] = *(const uint2*)(g_Whh + (size_t)sid[j] * OUTD + lane * 4);
        #pragma unroll
        for (int j = 0; j < 4; j++) {
            float2 p = __half22float2(*(__half2*)&uv[j].x);
            float2 q = __half22float2(*(__half2*)&uv[j].y);
            acc.x += av[j] * p.x; acc.y += av[j] * p.y;
            acc.z += av[j] * q.x; acc.w += av[j] * q.y;
            dsum  += av[j];
        }
        i += 4;
    }
    for (; i < end; i++) {
        int s0 = g_csrc[i];
        float a0 = g_attn2[i * NH + hh];
        uint2 u0 = *(const uint2*)(g_Whh + (size_t)s0 * OUTD + lane * 4);
        float2 p0 = __half22float2(*(__half2*)&u0.x), q0 = __half22float2(*(__half2*)&u0.y);
        acc.x += a0 * p0.x; acc.y += a0 * p0.y;
        acc.z += a0 * q0.x; acc.w += a0 * q0.y;
        dsum  += a0;
    }
    float inv = 1.f / (dsum + 1e-9f);
    float x0 = acc.x * inv, x1 = acc.y * inv, x2 = acc.z * inv, x3 = acc.w * inv;
    float g0 = 0.5f * x0 * (1.f + erff(x0 * 0.70710678118654752f));
    float g1 = 0.5f * x1 * (1.f + erff(x1 * 0.70710678118654752f));
    float g2 = 0.5f * x2 * (1.f + erff(x2 * 0.70710678118654752f));
    float g3 = 0.5f * x3 * (1.f + erff(x3 * 0.70710678118654752f));
    float s = g0 + g1 + g2 + g3;
    #pragma unroll
    for (int o = 16; o > 0; o >>= 1) s += __shfl_xor_sync(0xffffffffu, s, o);
    float mu = s * (1.f / OUTD);
    float d0 = g0 - mu, d1 = g1 - mu, d2 = g2 - mu, d3 = g3 - mu;
    float ss = d0 * d0 + d1 * d1 + d2 * d2 + d3 * d3;
    #pragma unroll
    for (int o = 16; o > 0; o >>= 1) ss += __shfl_xor_sync(0xffffffffu, ss, o);
    float invs = rsqrtf(ss * (1.f / OUTD) + 1e-5f);
    float4 sc = *(const float4*)(lns + lane * 4);
    float4 bi = *(const float4*)(lnb + lane * 4);
    float4 r;
    r.x = d0 * invs * sc.x + bi.x;
    r.y = d1 * invs * sc.y + bi.y;
    r.z = d2 * invs * sc.z + bi.z;
    r.w = d3 * invs * sc.w + bi.w;
    *(float4*)(out + (size_t)w * OUTD + lane * 4) = r;
}

// ---------------- launch ----------------------------------------------------
extern "C" void kernel_launch(void* const* d_in, const int* in_sizes, int n_in,
                              void* d_out, int out_size) {
    const float* h   = (const float*)d_in[0];
    const int*   ei  = (const int*)d_in[1];
    const float* ef  = (const float*)d_in[2];
    const float* W   = (const float*)d_in[3];
    const float* We  = (const float*)d_in[4];
    const float* a   = (const float*)d_in[5];
    const float* lns = (const float*)d_in[6];
    const float* lnb = (const float*)d_in[7];
    float* out = (float*)d_out;

    cudaFuncSetAttribute(k_gemm, cudaFuncAttributeMaxDynamicSharedMemorySize, GEMM_SMEM);

    k_prep<<<(NN + 255) / 256, 256>>>(ei);
    k_gemm<<<(NN + 63) / 64, 256, GEMM_SMEM>>>(h, W);
    k_scores<<<(NN * 32 + 255) / 256, 256>>>(a);
    k_edge<<<(NE + 255) / 256, 256>>>(ei, ef, We);
    k_scan1<<<NB, 512>>>();
    k_scan2<<<1, 128>>>();
    k_scan3<<<(NN + 255) / 256, 256>>>();
    k_scatter<<<(NE + 255) / 256, 256>>>(ei);
    k_aggpost<<<(NN * 32 + 255) / 256, 256>>>(lns, lnb, out);
}

// round 16
// speedup vs baseline: 1.2788x; 1.0988x over previous
#include <cuda_runtime.h>
#include <cuda_fp16.h>
#include <cuda_bf16.h>
#include <math.h>
#include <stdint.h>

#define NN    50000
#define NE    640000
#define IND   128
#define OUTD  128
#define EDIM  16
#define NH    4
#define HD    32
#define NB    ((NN + 511) / 512)   // scan blocks = 98

// bf16-split GEMM smem layout (uint32 pair units, row stride 68 ≡ 4 mod 32)
#define PJW   68
#define SW_H  0
#define SW_L  (128 * PJW)
#define SH_H  (256 * PJW)
#define SH_L  (256 * PJW + 64 * PJW)
#define GEMM_SMEM ((384 * PJW) * 4)    // 104448 bytes

// ---------------- scratch (device globals; no runtime alloc allowed) -------
__device__ __align__(16) __half g_Whh[NN * OUTD]; // fp16 projected features
__device__ __align__(16) float g_ssrc[NN * NH];
__device__ __align__(16) float g_sdst[NN * NH];
__device__ __align__(16) float g_attn[NE * NH];    // exp values, edge order
__device__ __align__(16) float g_attn2[NE * NH];   // exp values, CSR order
__device__ int   g_csrc[NE];                       // src node, CSR order
__device__ int   g_rank[NE];                       // rank of edge within dst
__device__ int   g_cnt[NN];
__device__ int   g_off[NN + 1];
__device__ int   g_bsum[128];
__device__ int   g_is64;

__device__ __forceinline__ int load_idx(const int* p32, int i, int is64) {
    return is64 ? p32[2 * i] : p32[i];   // int64 LE, values < 2^31
}

// ---------------- bf16 split helpers ---------------------------------------
__device__ __forceinline__ void bf16_split2(float x, float y, uint32_t& hi, uint32_t& lo) {
    __nv_bfloat162 h2 = __floats2bfloat162_rn(x, y);
    hi = *reinterpret_cast<uint32_t*>(&h2);
    float rx = x - __bfloat162float(h2.x);
    float ry = y - __bfloat162float(h2.y);
    __nv_bfloat162 l2 = __floats2bfloat162_rn(rx, ry);
    lo = *reinterpret_cast<uint32_t*>(&l2);
}
__device__ __forceinline__ void mma_bf16(float4& c, const uint32_t* a, const uint32_t* b) {
    asm volatile(
        "mma.sync.aligned.m16n8k16.row.col.f32.bf16.bf16.f32 "
        "{%0,%1,%2,%3}, {%4,%5,%6,%7}, {%8,%9}, {%0,%1,%2,%3};"
        : "+f"(c.x), "+f"(c.y), "+f"(c.z), "+f"(c.w)
        : "r"(a[0]), "r"(a[1]), "r"(a[2]), "r"(a[3]), "r"(b[0]), "r"(b[1]));
}

// ---------------- detect edge_index dtype + zero counts ---------------------
__global__ void k_prep(const int* __restrict__ ei32) {
    int t = blockIdx.x * blockDim.x + threadIdx.x;
    if (t < NN) g_cnt[t] = 0;
    if (t == 0) {
        int nz = 0;
        #pragma unroll 4
        for (int k = 0; k < 2048; k++) nz |= ei32[2 * k + 1];
        g_is64 = (nz == 0) ? 1 : 0;
    }
}

// ---------------- Wh = h @ W^T via pre-split bf16 MMA ----------------------
// block: 64 nodes x 128 outs, 8 warps (4 m-warps x 2 n-warps), K=128 (8 k16 steps)
__global__ void k_gemm(const float* __restrict__ h, const float* __restrict__ W) {
    extern __shared__ uint32_t sm[];
    const int tid  = threadIdx.x;
    const int n0b  = blockIdx.x * 64;
    const int lane = tid & 31;
    const int wid  = tid >> 5;
    const int mw   = wid & 3;         // m tile: 16 rows
    const int nw   = wid >> 2;        // n half: 64 cols
    const int grp  = lane >> 2;       // 0..7
    const int tig  = lane & 3;        // 0..3

    // load + split W (128x128) -> smem hi/lo bf16x2 pairs
    #pragma unroll
    for (int it = 0; it < 16; it++) {
        int f = it * 256 + tid;
        int o = f >> 5, c4 = (f & 31) * 4;
        float4 v = *(const float4*)(W + o * IND + c4);
        uint32_t h0, l0, h1, l1;
        bf16_split2(v.x, v.y, h0, l0);
        bf16_split2(v.z, v.w, h1, l1);
        int p = o * PJW + (c4 >> 1);
        sm[SW_H + p] = h0; sm[SW_H + p + 1] = h1;
        sm[SW_L + p] = l0; sm[SW_L + p + 1] = l1;
    }
    // load + split h tile (64x128), guarded
    #pragma unroll
    for (int it = 0; it < 8; it++) {
        int f = it * 256 + tid;
        int m = f >> 5, c4 = (f & 31) * 4;
        float4 v = make_float4(0.f, 0.f, 0.f, 0.f);
        if (n0b + m < NN) v = *(const float4*)(h + (size_t)(n0b + m) * IND + c4);
        uint32_t h0, l0, h1, l1;
        bf16_split2(v.x, v.y, h0, l0);
        bf16_split2(v.z, v.w, h1, l1);
        int p = m * PJW + (c4 >> 1);
        sm[SH_H + p] = h0; sm[SH_H + p + 1] = h1;
        sm[SH_L + p] = l0; sm[SH_L + p + 1] = l1;
    }
    __syncthreads();

    float4 acc[8];
    #pragma unroll
    for (int i = 0; i < 8; i++) acc[i] = make_float4(0.f, 0.f, 0.f, 0.f);

    const int m0  = mw * 16;
    const int nb0 = nw * 64;

    #pragma unroll
    for (int kp = 0; kp < 64; kp += 8) {   // 8 pairs = 16 k per step
        uint32_t ah[4], al[4];
        int ra0 = SH_H + (m0 + grp) * PJW + kp + tig;
        int ra1 = SH_H + (m0 + grp + 8) * PJW + kp + tig;
        ah[0] = sm[ra0];     ah[1] = sm[ra1];
        ah[2] = sm[ra0 + 4]; ah[3] = sm[ra1 + 4];
        const int dL = SH_L - SH_H;
        al[0] = sm[ra0 + dL];     al[1] = sm[ra1 + dL];
        al[2] = sm[ra0 + 4 + dL]; al[3] = sm[ra1 + 4 + dL];
        #pragma unroll
        for (int nt = 0; nt < 8; nt++) {
            int rb = (nb0 + nt * 8 + grp) * PJW + kp + tig;
            uint32_t bh[2] = { sm[SW_H + rb], sm[SW_H + rb + 4] };
            uint32_t bl[2] = { sm[SW_L + rb], sm[SW_L + rb + 4] };
            mma_bf16(acc[nt], ah, bh);
            mma_bf16(acc[nt], ah, bl);
            mma_bf16(acc[nt], al, bh);
        }
    }

    int node0 = n0b + m0 + grp;
    int node1 = node0 + 8;
    #pragma unroll
    for (int nt = 0; nt < 8; nt++) {
        int col = nb0 + nt * 8 + 2 * tig;
        if (node0 < NN)
            *(__half2*)(g_Whh + (size_t)node0 * OUTD + col) =
                __float22half2_rn(make_float2(acc[nt].x, acc[nt].y));
        if (node1 < NN)
            *(__half2*)(g_Whh + (size_t)node1 * OUTD + col) =
                __float22half2_rn(make_float2(acc[nt].z, acc[nt].w));
    }
}

// ---------------- per-node attention score halves (warp per node, fp16) ----
__global__ void k_scores(const float* __restrict__ a) {
    int w    = (blockIdx.x * blockDim.x + threadIdx.x) >> 5;
    int lane = threadIdx.x & 31;
    if (w >= NN) return;
    uint2 u = *(const uint2*)(g_Whh + (size_t)w * OUTD + lane * 4);
    float2 p = __half22float2(*(__half2*)&u.x);
    float2 q = __half22float2(*(__half2*)&u.y);
    int   hh  = lane >> 3;
    int   d0  = (lane & 7) * 4;
    float4 a1 = *(const float4*)(a + hh * (2 * HD) + d0);
    float4 a2 = *(const float4*)(a + hh * (2 * HD) + HD + d0);
    float s1  = p.x * a1.x + p.y * a1.y + q.x * a1.z + q.y * a1.w;
    float s2  = p.x * a2.x + p.y * a2.y + q.x * a2.z + q.y * a2.w;
    #pragma unroll
    for (int o = 4; o >= 1; o >>= 1) {
        s1 += __shfl_xor_sync(0xffffffffu, s1, o);
        s2 += __shfl_xor_sync(0xffffffffu, s2, o);
    }
    if ((lane & 7) == 0) {
        g_ssrc[w * NH + hh] = s1;
        g_sdst[w * NH + hh] = s2;
    }
}

// ---------------- edge logits -> exp, 2 edges per thread --------------------
__global__ void k_edge(const int* __restrict__ ei,
                       const float* __restrict__ ef,
                       const float* __restrict__ We) {
    __shared__ float sWe[NH * EDIM];
    if (threadIdx.x < NH * EDIM) sWe[threadIdx.x] = We[threadIdx.x];
    __syncthreads();
    int t  = blockIdx.x * blockDim.x + threadIdx.x;
    int e0 = t * 2;
    if (e0 >= NE) return;                // NE even: both edges valid
    int is64 = g_is64;
    int sA = load_idx(ei, e0, is64);
    int sB = load_idx(ei, e0 + 1, is64);
    int dA = load_idx(ei, NE + e0, is64);
    int dB = load_idx(ei, NE + e0 + 1, is64);
    // batch all 4 random score gathers
    float4 s1A = *(const float4*)(g_ssrc + sA * NH);
    float4 s1B = *(const float4*)(g_ssrc + sB * NH);
    float4 s2A = *(const float4*)(g_sdst + dA * NH);
    float4 s2B = *(const float4*)(g_sdst + dB * NH);
    const float4* efp = (const float4*)(ef + (size_t)e0 * EDIM);
    float4 ea0 = efp[0], ea1 = efp[1], ea2 = efp[2], ea3 = efp[3];
    float4 eb0 = efp[4], eb1 = efp[5], eb2 = efp[6], eb3 = efp[7];

    float sA4[4] = { s1A.x + s2A.x, s1A.y + s2A.y, s1A.z + s2A.z, s1A.w + s2A.w };
    float sB4[4] = { s1B.x + s2B.x, s1B.y + s2B.y, s1B.z + s2B.z, s1B.w + s2B.w };
    #pragma unroll
    for (int hh = 0; hh < 4; hh++) {
        sA4[hh] = (sA4[hh] > 0.f) ? sA4[hh] : 0.2f * sA4[hh];
        sB4[hh] = (sB4[hh] > 0.f) ? sB4[hh] : 0.2f * sB4[hh];
    }
    float evA[16] = { ea0.x, ea0.y, ea0.z, ea0.w, ea1.x, ea1.y, ea1.z, ea1.w,
                      ea2.x, ea2.y, ea2.z, ea2.w, ea3.x, ea3.y, ea3.z, ea3.w };
    float evB[16] = { eb0.x, eb0.y, eb0.z, eb0.w, eb1.x, eb1.y, eb1.z, eb1.w,
                      eb2.x, eb2.y, eb2.z, eb2.w, eb3.x, eb3.y, eb3.z, eb3.w };
    float4 rA, rB;
    #pragma unroll
    for (int hh = 0; hh < 4; hh++) {
        float dA_ = 0.f, dB_ = 0.f;
        #pragma unroll
        for (int k = 0; k < EDIM; k++) {
            float wv = sWe[hh * EDIM + k];
            dA_ += wv * evA[k];
            dB_ += wv * evB[k];
        }
        ((float*)&rA)[hh] = expf(sA4[hh] + dA_);
        ((float*)&rB)[hh] = expf(sB4[hh] + dB_);
    }
    *(float4*)(g_attn + (size_t)e0 * NH) = rA;
    *(float4*)(g_attn + (size_t)(e0 + 1) * NH) = rB;
    g_rank[e0]     = atomicAdd(&g_cnt[dA], 1);
    g_rank[e0 + 1] = atomicAdd(&g_cnt[dB], 1);
}

// ---------------- CSR build: scan (3 kernels) + atomic-free scatter ---------
__global__ void k_scan1() {
    __shared__ int sh[512];
    int i = blockIdx.x * 512 + threadIdx.x;
    int v = (i < NN) ? g_cnt[i] : 0;
    sh[threadIdx.x] = v;
    __syncthreads();
    for (int o = 1; o < 512; o <<= 1) {
        int t = (threadIdx.x >= o) ? sh[threadIdx.x - o] : 0;
        __syncthreads();
        sh[threadIdx.x] += t;
        __syncthreads();
    }
    int incl = sh[threadIdx.x];
    if (i < NN) g_off[i] = incl - v;
    if (threadIdx.x == 511) g_bsum[blockIdx.x] = incl;
}

__global__ void k_scan2() {
    __shared__ int sh[128];
    int i = threadIdx.x;
    int v = (i < NB) ? g_bsum[i] : 0;
    sh[i] = v;
    __syncthreads();
    for (int o = 1; o < 128; o <<= 1) {
        int t = (i >= o) ? sh[i - o] : 0;
        __syncthreads();
        sh[i] += t;
        __syncthreads();
    }
    g_bsum[i] = sh[i] - v;
    if (i == 0) g_off[NN] = NE;
}

__global__ void k_scan3() {
    int i = blockIdx.x * blockDim.x + threadIdx.x;
    if (i >= NN) return;
    g_off[i] = g_off[i] + g_bsum[i >> 9];
}

__global__ void k_scatter(const int* __restrict__ ei) {
    int e = blockIdx.x * blockDim.x + threadIdx.x;
    if (e >= NE) return;
    int is64 = g_is64;
    int src = load_idx(ei, e, is64);
    int dst = load_idx(ei, NE + e, is64);
    int pos = g_off[dst] + g_rank[e];
    g_csrc[pos] = src;
    float4 v = *(const float4*)(g_attn + (size_t)e * NH);
    *(float4*)(g_attn2 + (size_t)pos * NH) = v;
}

// ---------------- gather-aggregate (fp16 feats) + softmax + gelu + LN ------
__global__ void k_aggpost(const float* __restrict__ lns,
                          const float* __restrict__ lnb,
                          float* __restrict__ out) {
    int w    = (blockIdx.x * blockDim.x + threadIdx.x) >> 5;
    int lane = threadIdx.x & 31;
    if (w >= NN) return;
    int beg = g_off[w], end = g_off[w + 1];
    int hh  = lane >> 3;
    float4 acc = make_float4(0.f, 0.f, 0.f, 0.f);
    float dsum = 0.f;
    int i = beg;
    for (; i + 4 <= end; i += 4) {
        int s0 = g_csrc[i], s1 = g_csrc[i + 1], s2 = g_csrc[i + 2], s3 = g_csrc[i + 3];
        float a0 = g_attn2[(i + 0) * NH + hh];
        float a1 = g_attn2[(i + 1) * NH + hh];
        float a2 = g_attn2[(i + 2) * NH + hh];
        float a3 = g_attn2[(i + 3) * NH + hh];
        uint2 u0 = *(const uint2*)(g_Whh + (size_t)s0 * OUTD + lane * 4);
        uint2 u1 = *(const uint2*)(g_Whh + (size_t)s1 * OUTD + lane * 4);
        uint2 u2 = *(const uint2*)(g_Whh + (size_t)s2 * OUTD + lane * 4);
        uint2 u3 = *(const uint2*)(g_Whh + (size_t)s3 * OUTD + lane * 4);
        float2 p0 = __half22float2(*(__half2*)&u0.x), q0 = __half22float2(*(__half2*)&u0.y);
        float2 p1 = __half22float2(*(__half2*)&u1.x), q1 = __half22float2(*(__half2*)&u1.y);
        float2 p2 = __half22float2(*(__half2*)&u2.x), q2 = __half22float2(*(__half2*)&u2.y);
        float2 p3 = __half22float2(*(__half2*)&u3.x), q3 = __half22float2(*(__half2*)&u3.y);
        acc.x += a0 * p0.x + a1 * p1.x + a2 * p2.x + a3 * p3.x;
        acc.y += a0 * p0.y + a1 * p1.y + a2 * p2.y + a3 * p3.y;
        acc.z += a0 * q0.x + a1 * q1.x + a2 * q2.x + a3 * q3.x;
        acc.w += a0 * q0.y + a1 * q1.y + a2 * q2.y + a3 * q3.y;
        dsum  += a0 + a1 + a2 + a3;
    }
    for (; i < end; i++) {
        int s0 = g_csrc[i];
        float a0 = g_attn2[i * NH + hh];
        uint2 u0 = *(const uint2*)(g_Whh + (size_t)s0 * OUTD + lane * 4);
        float2 p0 = __half22float2(*(__half2*)&u0.x), q0 = __half22float2(*(__half2*)&u0.y);
        acc.x += a0 * p0.x; acc.y += a0 * p0.y;
        acc.z += a0 * q0.x; acc.w += a0 * q0.y;
        dsum  += a0;
    }
    float inv = 1.f / (dsum + 1e-9f);
    float x0 = acc.x * inv, x1 = acc.y * inv, x2 = acc.z * inv, x3 = acc.w * inv;
    float g0 = 0.5f * x0 * (1.f + erff(x0 * 0.70710678118654752f));
    float g1 = 0.5f * x1 * (1.f + erff(x1 * 0.70710678118654752f));
    float g2 = 0.5f * x2 * (1.f + erff(x2 * 0.70710678118654752f));
    float g3 = 0.5f * x3 * (1.f + erff(x3 * 0.70710678118654752f));
    float s = g0 + g1 + g2 + g3;
    #pragma unroll
    for (int o = 16; o > 0; o >>= 1) s += __shfl_xor_sync(0xffffffffu, s, o);
    float mu = s * (1.f / OUTD);
    float d0 = g0 - mu, d1 = g1 - mu, d2 = g2 - mu, d3 = g3 - mu;
    float ss = d0 * d0 + d1 * d1 + d2 * d2 + d3 * d3;
    #pragma unroll
    for (int o = 16; o > 0; o >>= 1) ss += __shfl_xor_sync(0xffffffffu, ss, o);
    float invs = rsqrtf(ss * (1.f / OUTD) + 1e-5f);
    float4 sc = *(const float4*)(lns + lane * 4);
    float4 bi = *(const float4*)(lnb + lane * 4);
    float4 r;
    r.x = d0 * invs * sc.x + bi.x;
    r.y = d1 * invs * sc.y + bi.y;
    r.z = d2 * invs * sc.z + bi.z;
    r.w = d3 * invs * sc.w + bi.w;
    *(float4*)(out + (size_t)w * OUTD + lane * 4) = r;
}

// ---------------- launch ----------------------------------------------------
extern "C" void kernel_launch(void* const* d_in, const int* in_sizes, int n_in,
                              void* d_out, int out_size) {
    const float* h   = (const float*)d_in[0];
    const int*   ei  = (const int*)d_in[1];
    const float* ef  = (const float*)d_in[2];
    const float* W   = (const float*)d_in[3];
    const float* We  = (const float*)d_in[4];
    const float* a   = (const float*)d_in[5];
    const float* lns = (const float*)d_in[6];
    const float* lnb = (const float*)d_in[7];
    float* out = (float*)d_out;

    cudaFuncSetAttribute(k_gemm, cudaFuncAttributeMaxDynamicSharedMemorySize, GEMM_SMEM);

    k_prep<<<(NN + 255) / 256, 256>>>(ei);
    k_gemm<<<(NN + 63) / 64, 256, GEMM_SMEM>>>(h, W);
    k_scores<<<(NN * 32 + 255) / 256, 256>>>(a);
    k_edge<<<(NE / 2 + 255) / 256, 256>>>(ei, ef, We);
    k_scan1<<<NB, 512>>>();
    k_scan2<<<1, 128>>>();
    k_scan3<<<(NN + 255) / 256, 256>>>();
    k_scatter<<<(NE + 255) / 256, 256>>>(ei);
    k_aggpost<<<(NN * 32 + 255) / 256, 256>>>(lns, lnb, out);
}